// round 15
// baseline (speedup 1.0000x reference)
#include <cuda_runtime.h>
#include <cuda_bf16.h>

// CRF NLL: B=1024, T=512, K=64, START=62, STOP=63
// Exp-domain forward recursion in BF16 with SMEM broadcast:
// persistent warps (148 CTAs x 4 = 592, one per SMSP), LPT via atomic counter.
// v[64] = 32 bf16x2 words in shared (128 B): broadcast = 8x LDS.128 preloaded
// into registers, matvec = 64 HFMA2 on 4 chains. One STS.32 + syncwarp/step,
// double-buffered. Emission exp + scaling in fp32. Et = bf16(exp(trans)).

#define B_ 1024
#define T_ 512
#define K_ 64
#define START_ 62
#define STOP_ 63

typedef unsigned int u32;

__device__ int g_order[B_];
__device__ int g_counter;

__device__ __forceinline__ __nv_bfloat162 as_bf2(u32 x) {
    return *reinterpret_cast<__nv_bfloat162*>(&x);
}
__device__ __forceinline__ u32 as_u32(__nv_bfloat162 x) {
    return *reinterpret_cast<u32*>(&x);
}

// Rank batches by descending length; zero accumulator + work counter.
__global__ void order_kernel(const int* __restrict__ lengths, float* out) {
    __shared__ int L[B_];
    const int tid = threadIdx.x;                 // 256 threads, grid 4
    for (int j = tid; j < B_; j += 256) L[j] = lengths[j];
    __syncthreads();
    const int b = blockIdx.x * 256 + tid;
    const int mylen = L[b];
    int rank = 0;
    for (int j = 0; j < B_; ++j) {
        int lj = L[j];
        rank += (lj > mylen) || (lj == mylen && j < b);
    }
    g_order[rank] = b;
    if (b == 0) { out[0] = 0.0f; g_counter = 0; }
}

__global__ void __launch_bounds__(128, 1) crf_bf16s(
    const float* __restrict__ feats,      // [B,T,K]
    const int*   __restrict__ lengths,    // [B]
    const int*   __restrict__ tags,       // [B,T]
    const float* __restrict__ trans,      // [K,K] trans[next, prev]
    float* __restrict__ out)
{
    // [warp][buf][32 bf16x2 words]; 16B-aligned for LDS.128
    __shared__ __align__(16) u32 vbuf[4][2][32];

    const int lane = threadIdx.x & 31;    // owns rows/elems 2*lane, 2*lane+1
    const int w    = threadIdx.x >> 5;

    // ---- Et rows 2*lane, 2*lane+1 as bf16x2 over column pairs; once/warp ----
    __nv_bfloat162 EtA[32], EtB[32];
#pragma unroll
    for (int q = 0; q < 32; ++q) {
        EtA[q] = __floats2bfloat162_rn(__expf(trans[(2 * lane)     * K_ + 2 * q]),
                                       __expf(trans[(2 * lane)     * K_ + 2 * q + 1]));
        EtB[q] = __floats2bfloat162_rn(__expf(trans[(2 * lane + 1) * K_ + 2 * q]),
                                       __expf(trans[(2 * lane + 1) * K_ + 2 * q + 1]));
    }
    const float EtS0 = __expf(trans[STOP_ * K_ + 2 * lane]);
    const float EtS1 = __expf(trans[STOP_ * K_ + 2 * lane + 1]);

    for (;;) {
        // ---- grab next batch (longest remaining first) ----
        int r = 0;
        if (lane == 0) r = atomicAdd(&g_counter, 1);
        r = __shfl_sync(0xFFFFFFFFu, r, 0);
        if (r >= B_) break;
        const int b   = g_order[r];
        const int len = lengths[b];

        const float*  fb  = feats + (size_t)b * (T_ * K_);
        const float2* fb2 = (const float2*)fb;          // [T][32]
        const int*    tb  = tags + (size_t)b * T_;

        // ---- gold score, parallel over t (fp32, exact) ----
        float gold = 0.0f;
#pragma unroll
        for (int q = 0; q < 16; ++q) {
            int t = lane + 32 * q;
            if (t < len) {
                int tg = tb[t];
                int pv = t ? tb[t - 1] : START_;
                gold += fb[t * K_ + tg] + trans[tg * K_ + pv];
            }
        }
        if (lane == 0) gold += trans[STOP_ * K_ + tb[len - 1]];

        // ---- v0 packed into buf 0 ----
        vbuf[w][0][lane] = as_u32(__floats2bfloat162_rn(
            (2 * lane     == START_) ? 1.0f : 0.0f,
            (2 * lane + 1 == START_) ? 1.0f : 0.0f));

        // ---- emission group 0..3, exp'd in fp32 ----
        float2 c0 = fb2[0 * 32 + lane], c1 = fb2[1 * 32 + lane],
               c2 = fb2[2 * 32 + lane], c3 = fb2[3 * 32 + lane];
        float2 ce0 = make_float2(__expf(c0.x), __expf(c0.y));
        float2 ce1 = make_float2(__expf(c1.x), __expf(c1.y));
        float2 ce2 = make_float2(__expf(c2.x), __expf(c2.y));
        float2 ce3 = make_float2(__expf(c3.x), __expf(c3.y));
        __syncwarp();

        int ktot = 0, cur = 0;
        const int len4 = len & ~3;

        // One step: 8x LDS.128 preload (batched, broadcast, conflict-free),
        // 64 HFMA2 on 4 chains, fp32 epilogue, STS.32, syncwarp.
#define STEP(CE, RESC)                                                     \
    {                                                                      \
        const uint4* vv = (const uint4*)vbuf[w][cur];                      \
        uint4 xq[8];                                                       \
        _Pragma("unroll")                                                  \
        for (int q = 0; q < 8; ++q) xq[q] = vv[q];                         \
        __nv_bfloat162 z = __floats2bfloat162_rn(0.f, 0.f);                \
        __nv_bfloat162 aA0 = z, aA1 = z, aB0 = z, aB1 = z;                 \
        _Pragma("unroll")                                                  \
        for (int q = 0; q < 8; ++q) {                                      \
            __nv_bfloat162 p0 = as_bf2(xq[q].x), p1 = as_bf2(xq[q].y);     \
            __nv_bfloat162 p2 = as_bf2(xq[q].z), p3 = as_bf2(xq[q].w);     \
            aA0 = __hfma2(EtA[4 * q + 0], p0, aA0);                        \
            aB0 = __hfma2(EtB[4 * q + 0], p0, aB0);                        \
            aA1 = __hfma2(EtA[4 * q + 1], p1, aA1);                        \
            aB1 = __hfma2(EtB[4 * q + 1], p1, aB1);                        \
            aA0 = __hfma2(EtA[4 * q + 2], p2, aA0);                        \
            aB0 = __hfma2(EtB[4 * q + 2], p2, aB0);                        \
            aA1 = __hfma2(EtA[4 * q + 3], p3, aA1);                        \
            aB1 = __hfma2(EtB[4 * q + 3], p3, aB1);                        \
        }                                                                  \
        float2 fA = __bfloat1622float2(__hadd2(aA0, aA1));                 \
        float2 fB = __bfloat1622float2(__hadd2(aB0, aB1));                 \
        float w0 = (fA.x + fA.y) * (CE).x;                                 \
        float w1 = (fB.x + fB.y) * (CE).y;                                 \
        if (RESC) {                                                        \
            __nv_bfloat162 mh = z;                                         \
            _Pragma("unroll")                                              \
            for (int q = 0; q < 8; ++q) {                                  \
                mh = __hmax2(mh, as_bf2(xq[q].x));                         \
                mh = __hmax2(mh, as_bf2(xq[q].y));                         \
                mh = __hmax2(mh, as_bf2(xq[q].z));                         \
                mh = __hmax2(mh, as_bf2(xq[q].w));                         \
            }                                                              \
            float2 m2 = __bfloat1622float2(mh);                            \
            float mx = fmaxf(m2.x, m2.y);                                  \
            /* mx identical on all lanes: built from the shared v */       \
            if (mx > 0.0f) {                                               \
                int k = ((__float_as_int(mx) >> 23) & 0xFF) - 127;         \
                ktot += k;                                                 \
                float sc = __int_as_float((127 - k) << 23);                \
                w0 *= sc; w1 *= sc;                                        \
            }                                                              \
        }                                                                  \
        cur ^= 1;                                                          \
        vbuf[w][cur][lane] = as_u32(__floats2bfloat162_rn(w0, w1));        \
        __syncwarp();                                                      \
    }

        for (int t0 = 0; t0 < len4; t0 += 4) {
            // load next group's raw emissions (clamped; garbage never used)
            const int p = min(t0 + 4, T_ - 4);
            float2 g0 = fb2[(p + 0) * 32 + lane];
            float2 g1 = fb2[(p + 1) * 32 + lane];
            float2 g2 = fb2[(p + 2) * 32 + lane];
            float2 g3 = fb2[(p + 3) * 32 + lane];

            STEP(ce0, false);
            STEP(ce1, false);
            STEP(ce2, false);
            STEP(ce3, true);

            ce0 = make_float2(__expf(g0.x), __expf(g0.y));
            ce1 = make_float2(__expf(g1.x), __expf(g1.y));
            ce2 = make_float2(__expf(g2.x), __expf(g2.y));
            ce3 = make_float2(__expf(g3.x), __expf(g3.y));
        }

        // remainder (0-3 steps; <=3 unscaled steps cannot overflow bf16)
        const int rem = len - len4;
        if (rem > 0) STEP(ce0, false);
        if (rem > 1) STEP(ce1, false);
        if (rem > 2) STEP(ce2, false);
#undef STEP

        // ---- terminal: fwd = ktot*ln2 + log(sum_i v[i]*exp(trans[STOP,i])) --
        float2 vf = __bfloat1622float2(as_bf2(vbuf[w][cur][lane]));
        float u = vf.x * EtS0 + vf.y * EtS1;
#pragma unroll
        for (int off = 16; off; off >>= 1) {
            u    += __shfl_xor_sync(0xFFFFFFFFu, u,    off);
            gold += __shfl_xor_sync(0xFFFFFFFFu, gold, off);
        }
        if (lane == 0) {
            float fwd = (float)((double)ktot * 0.69314718055994530942)
                      + logf(u);
            atomicAdd(out, (fwd - gold) * (1.0f / (float)B_));
        }
        __syncwarp();
    }
}

extern "C" void kernel_launch(void* const* d_in, const int* in_sizes, int n_in,
                              void* d_out, int out_size)
{
    const float* feats   = (const float*)d_in[0];
    const int*   lengths = (const int*)  d_in[1];
    const int*   tags    = (const int*)  d_in[2];
    const float* trans   = (const float*)d_in[3];
    float* out = (float*)d_out;

    order_kernel<<<4, 256>>>(lengths, out);
    crf_bf16s<<<148, 128>>>(feats, lengths, tags, trans, out);
}